// round 11
// baseline (speedup 1.0000x reference)
#include <cuda_runtime.h>
#include <cstdint>

// ---------------------------------------------------------------------------
// Problem constants
// ---------------------------------------------------------------------------
#define BATCH 16
#define CDIM  768
#define SDIM  4096          // H*W = 64*64
#define KCOND 1024

#define PIX     32          // pixels per LN block
#define THREADS 256
#define REG_IT  12          // c-iterations kept in registers (of 24)

// ---------------------------------------------------------------------------
// Scratch (no allocations allowed -> device globals)
// ---------------------------------------------------------------------------
__device__ __align__(16) float g_tmp0[BATCH * CDIM];
__device__ __align__(16) float g_tmp1[BATCH * CDIM];

// ---------------------------------------------------------------------------
// Small GEMM: out[b,n] = bias[n] + sum_k X[b,k] * W[n,k], B=16 fixed.
// Warp micro-tile = 4 columns x 4 batches (16 accumulators):
//   8 float4 loads per k4-iter feed 16 outputs -> 3x fewer LDGs/output than
//   the 1x2 scheme. Block 256 = 8 warps = 4 batch-groups x 2 K-halves.
// Grid = N/4 = 192. Reduction: SMEM transpose, 64 threads finalize.
// ---------------------------------------------------------------------------
template<int K4>
__global__ void __launch_bounds__(256) gemm16_4x4(
    const float* __restrict__ X, const float* __restrict__ W,
    const float* __restrict__ bias, float* __restrict__ out, int N)
{
    constexpr int KH = K4 / 2;               // per-warp K4 half
    const int tid  = threadIdx.x;
    const int warp = tid >> 5;               // 0..7
    const int lane = tid & 31;
    const int kg   = warp & 1;               // K half
    const int bg   = warp >> 1;              // batch group 0..3
    const int n0   = blockIdx.x * 4;
    const int b0   = bg * 4;

    const float4* W4 = (const float4*)W;
    const float4* X4 = (const float4*)X;

    float acc[16];
#pragma unroll
    for (int a = 0; a < 16; a++) acc[a] = 0.f;

#pragma unroll
    for (int i = 0; i < KH / 32; i++) {
        const int k4 = kg * KH + lane + i * 32;
        float4 w0 = __ldg(W4 + (size_t)(n0 + 0) * K4 + k4);
        float4 w1 = __ldg(W4 + (size_t)(n0 + 1) * K4 + k4);
        float4 w2 = __ldg(W4 + (size_t)(n0 + 2) * K4 + k4);
        float4 w3 = __ldg(W4 + (size_t)(n0 + 3) * K4 + k4);
        float4 x0 = __ldg(X4 + (size_t)(b0 + 0) * K4 + k4);
        float4 x1 = __ldg(X4 + (size_t)(b0 + 1) * K4 + k4);
        float4 x2 = __ldg(X4 + (size_t)(b0 + 2) * K4 + k4);
        float4 x3 = __ldg(X4 + (size_t)(b0 + 3) * K4 + k4);

        acc[ 0] += x0.x*w0.x + x0.y*w0.y + x0.z*w0.z + x0.w*w0.w;
        acc[ 1] += x0.x*w1.x + x0.y*w1.y + x0.z*w1.z + x0.w*w1.w;
        acc[ 2] += x0.x*w2.x + x0.y*w2.y + x0.z*w2.z + x0.w*w2.w;
        acc[ 3] += x0.x*w3.x + x0.y*w3.y + x0.z*w3.z + x0.w*w3.w;
        acc[ 4] += x1.x*w0.x + x1.y*w0.y + x1.z*w0.z + x1.w*w0.w;
        acc[ 5] += x1.x*w1.x + x1.y*w1.y + x1.z*w1.z + x1.w*w1.w;
        acc[ 6] += x1.x*w2.x + x1.y*w2.y + x1.z*w2.z + x1.w*w2.w;
        acc[ 7] += x1.x*w3.x + x1.y*w3.y + x1.z*w3.z + x1.w*w3.w;
        acc[ 8] += x2.x*w0.x + x2.y*w0.y + x2.z*w0.z + x2.w*w0.w;
        acc[ 9] += x2.x*w1.x + x2.y*w1.y + x2.z*w1.z + x2.w*w1.w;
        acc[10] += x2.x*w2.x + x2.y*w2.y + x2.z*w2.z + x2.w*w2.w;
        acc[11] += x2.x*w3.x + x2.y*w3.y + x2.z*w3.z + x2.w*w3.w;
        acc[12] += x3.x*w0.x + x3.y*w0.y + x3.z*w0.z + x3.w*w0.w;
        acc[13] += x3.x*w1.x + x3.y*w1.y + x3.z*w1.z + x3.w*w1.w;
        acc[14] += x3.x*w2.x + x3.y*w2.y + x3.z*w2.z + x3.w*w2.w;
        acc[15] += x3.x*w3.x + x3.y*w3.y + x3.z*w3.z + x3.w*w3.w;
    }

    // partials -> smem (stride 33 to dodge the worst conflicts)
    __shared__ float part[8 * 16 * 33];
#pragma unroll
    for (int a = 0; a < 16; a++)
        part[(warp * 16 + a) * 33 + lane] = acc[a];
    __syncthreads();

    // 64 outputs: thread t sums 2 K-halves x 32 lanes
    if (tid < 64) {
        const int bg2 = tid >> 4;            // batch group
        const int a   = tid & 15;            // bl*4 + cl
        float s = 0.f;
#pragma unroll
        for (int w2 = 0; w2 < 2; w2++) {
            const int row = (bg2 * 2 + w2) * 16 + a;
#pragma unroll 8
            for (int l = 0; l < 32; l++)
                s += part[row * 33 + l];
        }
        const int b = bg2 * 4 + (a >> 2);
        const int n = n0 + (a & 3);
        out[b * N + n] = s + __ldg(bias + n);
    }
}

// ---------------------------------------------------------------------------
// Fused broadcast-add + LayerNorm(C). Hybrid tile: 12 c-rows per thread in
// registers + 12 c-rows in SMEM (48 KB) -> 3 blocks/SM.
// Thread map: p4 = tid&7 (float4 slot of 32-pixel row), c0 = tid>>3 (0..31).
// Spatial read exactly once from DRAM.
// ---------------------------------------------------------------------------
__global__ void __launch_bounds__(THREADS, 3) fused_add_ln(
    const float* __restrict__ spatial,
    const float* __restrict__ proj,
    const float* __restrict__ gamma,
    const float* __restrict__ beta,
    float* __restrict__ out)
{
    extern __shared__ float smem[];
    float* tile   = smem;                              // (24-REG_IT)*32*PIX
    float* psum   = tile + (24 - REG_IT) * 32 * PIX;   // 8*PIX
    float* psq    = psum + 8 * PIX;                    // 8*PIX
    float* mean_s = psq  + 8 * PIX;                    // PIX
    float* rstd_s = mean_s + PIX;                      // PIX

    const int tid = threadIdx.x;
    const int b   = blockIdx.x >> 7;          // SDIM/PIX = 128 blocks/batch
    const int s0  = (blockIdx.x & 127) * PIX;

    const int p4   = tid & 7;                 // float4 slot within 32-pixel row
    const int c0   = tid >> 3;                // 0..31
    const int warp = tid >> 5;
    const int lane = tid & 31;

    const size_t gbase = (size_t)b * CDIM * SDIM + s0 + p4 * 4;
    const float* projb = proj + b * CDIM;

    float4 v[REG_IT];
    float acc[4] = {0.f, 0.f, 0.f, 0.f};
    float asq[4] = {0.f, 0.f, 0.f, 0.f};

    // ---- load + broadcast add + register stats (one DRAM read) ----
#pragma unroll
    for (int it = 0; it < 24; it++) {
        const int c = c0 + it * 32;
        float4 x = *(const float4*)(spatial + gbase + (size_t)c * SDIM);
        float pj = __ldg(projb + c);
        x.x += pj; x.y += pj; x.z += pj; x.w += pj;
        acc[0] += x.x; asq[0] += x.x * x.x;
        acc[1] += x.y; asq[1] += x.y * x.y;
        acc[2] += x.z; asq[2] += x.z * x.z;
        acc[3] += x.w; asq[3] += x.w * x.w;
        if (it < REG_IT) {
            v[it] = x;
        } else {
            *(float4*)(tile + ((it - REG_IT) * 32 + c0) * PIX + p4 * 4) = x;
        }
    }

    // ---- combine the 4 same-p4 lanes of this warp (lane bits 3,4) ----
#pragma unroll
    for (int q = 0; q < 4; q++) {
        acc[q] += __shfl_xor_sync(0xffffffffu, acc[q], 8);
        acc[q] += __shfl_xor_sync(0xffffffffu, acc[q], 16);
        asq[q] += __shfl_xor_sync(0xffffffffu, asq[q], 8);
        asq[q] += __shfl_xor_sync(0xffffffffu, asq[q], 16);
    }
    if (lane == p4) {                         // lanes 0..7
#pragma unroll
        for (int q = 0; q < 4; q++) {
            psum[warp * PIX + p4 * 4 + q] = acc[q];
            psq [warp * PIX + p4 * 4 + q] = asq[q];
        }
    }
    __syncthreads();

    // ---- final per-pixel stats ----
    if (tid < PIX) {
        float s = 0.f, sq = 0.f;
#pragma unroll
        for (int w = 0; w < 8; w++) { s += psum[w * PIX + tid]; sq += psq[w * PIX + tid]; }
        const float inv = 1.0f / CDIM;
        float mu  = s * inv;
        float var = sq * inv - mu * mu;
        mean_s[tid] = mu;
        rstd_s[tid] = rsqrtf(var + 1e-5f);
    }
    __syncthreads();

    // ---- normalize + store (register rows first, then smem rows) ----
    const float4 mu4 = *(const float4*)(mean_s + p4 * 4);
    const float4 rs4 = *(const float4*)(rstd_s + p4 * 4);
#pragma unroll
    for (int it = 0; it < REG_IT; it++) {
        const int c = c0 + it * 32;
        float g  = __ldg(gamma + c);
        float bt = __ldg(beta + c);
        float4 x = v[it];
        x.x = (x.x - mu4.x) * rs4.x * g + bt;
        x.y = (x.y - mu4.y) * rs4.y * g + bt;
        x.z = (x.z - mu4.z) * rs4.z * g + bt;
        x.w = (x.w - mu4.w) * rs4.w * g + bt;
        *(float4*)(out + gbase + (size_t)c * SDIM) = x;
    }
#pragma unroll
    for (int it = REG_IT; it < 24; it++) {
        const int c = c0 + it * 32;
        float g  = __ldg(gamma + c);
        float bt = __ldg(beta + c);
        float4 x = *(const float4*)(tile + ((it - REG_IT) * 32 + c0) * PIX + p4 * 4);
        x.x = (x.x - mu4.x) * rs4.x * g + bt;
        x.y = (x.y - mu4.y) * rs4.y * g + bt;
        x.z = (x.z - mu4.z) * rs4.z * g + bt;
        x.w = (x.w - mu4.w) * rs4.w * g + bt;
        *(float4*)(out + gbase + (size_t)c * SDIM) = x;
    }
}

// ---------------------------------------------------------------------------
// Launcher
// ---------------------------------------------------------------------------
extern "C" void kernel_launch(void* const* d_in, const int* in_sizes, int n_in,
                              void* d_out, int out_size)
{
    const float* spatial     = (const float*)d_in[0];
    const float* conditioning= (const float*)d_in[1];
    const float* w_cond      = (const float*)d_in[2];
    const float* b_cond      = (const float*)d_in[3];
    const float* in_proj_w   = (const float*)d_in[4];
    const float* in_proj_b   = (const float*)d_in[5];
    const float* attn_out_w  = (const float*)d_in[6];
    const float* attn_out_b  = (const float*)d_in[7];
    const float* w_out       = (const float*)d_in[8];
    const float* b_out       = (const float*)d_in[9];
    const float* ln_gamma    = (const float*)d_in[10];
    const float* ln_beta     = (const float*)d_in[11];
    float* out = (float*)d_out;

    float *tmp0, *tmp1;
    cudaGetSymbolAddress((void**)&tmp0, g_tmp0);
    cudaGetSymbolAddress((void**)&tmp1, g_tmp1);

    const int smem_bytes =
        ((24 - REG_IT) * 32 * PIX + 16 * PIX + 2 * PIX) * sizeof(float);
    cudaFuncSetAttribute(fused_add_ln, cudaFuncAttributeMaxDynamicSharedMemorySize,
                         smem_bytes);

    // 4-GEMM chain: 4x4 warp micro-tiles, grid = N/4 = 192, block 256
    gemm16_4x4<KCOND / 4><<<CDIM / 4, 256>>>(conditioning, w_cond, b_cond, tmp0, CDIM);
    gemm16_4x4<CDIM  / 4><<<CDIM / 4, 256>>>(tmp0, in_proj_w + 2 * CDIM * CDIM,
                                             in_proj_b + 2 * CDIM, tmp1, CDIM);
    gemm16_4x4<CDIM  / 4><<<CDIM / 4, 256>>>(tmp1, attn_out_w, attn_out_b, tmp0, CDIM);
    gemm16_4x4<CDIM  / 4><<<CDIM / 4, 256>>>(tmp0, w_out, b_out, tmp1, CDIM);

    // fused add + layernorm (proj lives in g_tmp1)
    fused_add_ln<<<BATCH * (SDIM / PIX), THREADS, smem_bytes>>>(
        spatial, tmp1, ln_gamma, ln_beta, out);
}

// round 12
// speedup vs baseline: 1.0269x; 1.0269x over previous
#include <cuda_runtime.h>
#include <cstdint>

// ---------------------------------------------------------------------------
// Problem constants
// ---------------------------------------------------------------------------
#define BATCH 16
#define CDIM  768
#define SDIM  4096          // H*W = 64*64
#define KCOND 1024

#define PIX     32          // pixels per LN block
#define THREADS 256
#define REG_IT  12          // c-iterations kept in registers (of 24)

#define GBLK    384         // chain grid: 384 blocks x 8 warps = 3072 warps

// ---------------------------------------------------------------------------
// Scratch (no allocations allowed -> device globals)
// ---------------------------------------------------------------------------
__device__ __align__(16) float g_tmp0[BATCH * CDIM];
__device__ __align__(16) float g_tmp1[BATCH * CDIM];
__device__ unsigned g_barrier;

// ---------------------------------------------------------------------------
// Grid-wide software barrier. ALL GBLK blocks are co-resident:
// __launch_bounds__(256,4) -> >=4 blocks/SM -> capacity 592 >= 384.
// Counter reset to 0 by a memset node before each launch.
// ---------------------------------------------------------------------------
__device__ __forceinline__ void grid_sync(unsigned target) {
    __syncthreads();
    if (threadIdx.x == 0) {
        __threadfence();                       // release our writes
        atomicAdd(&g_barrier, 1u);
        volatile unsigned* p = &g_barrier;
        while (*p < target) __nanosleep(64);
        __threadfence();                       // acquire others' writes
    }
    __syncthreads();
}

// ---------------------------------------------------------------------------
// One GEMM phase: out[b,n] = bias[n] + sum_k X[b,k] * W[n,k], B=16, N=768.
// 3072 warps: warp -> (column n, batch quad). Fully-unrolled K loop:
// 5 float4 LDGs per iter, 30-40 outstanding loads per warp.
// XCG: X written by a previous phase -> bypass (possibly stale) L1.
// ---------------------------------------------------------------------------
template<int K4, bool XCG>
__device__ __forceinline__ void gemm_phase(
    const float* __restrict__ X, const float* __restrict__ W,
    const float* __restrict__ bias, float* __restrict__ out)
{
    const int gw   = blockIdx.x * 8 + (threadIdx.x >> 5);  // 0..3071
    const int lane = threadIdx.x & 31;
    const int n    = gw >> 2;                 // 0..767
    const int b0   = (gw & 3) * 4;            // batch quad

    const float4* W4 = (const float4*)W + (size_t)n * K4;
    const float4* X4 = (const float4*)X + (size_t)b0 * K4;

    float a0 = 0.f, a1 = 0.f, a2 = 0.f, a3 = 0.f;
#pragma unroll
    for (int i = 0; i < K4 / 32; i++) {
        const int k4 = lane + i * 32;
        float4 w  = __ldg(W4 + k4);
        float4 x0 = XCG ? __ldcg(X4 + k4)          : __ldg(X4 + k4);
        float4 x1 = XCG ? __ldcg(X4 + K4 + k4)     : __ldg(X4 + K4 + k4);
        float4 x2 = XCG ? __ldcg(X4 + 2 * K4 + k4) : __ldg(X4 + 2 * K4 + k4);
        float4 x3 = XCG ? __ldcg(X4 + 3 * K4 + k4) : __ldg(X4 + 3 * K4 + k4);
        a0 += w.x*x0.x + w.y*x0.y + w.z*x0.z + w.w*x0.w;
        a1 += w.x*x1.x + w.y*x1.y + w.z*x1.z + w.w*x1.w;
        a2 += w.x*x2.x + w.y*x2.y + w.z*x2.z + w.w*x2.w;
        a3 += w.x*x3.x + w.y*x3.y + w.z*x3.z + w.w*x3.w;
    }
#pragma unroll
    for (int off = 16; off; off >>= 1) {
        a0 += __shfl_xor_sync(0xffffffffu, a0, off);
        a1 += __shfl_xor_sync(0xffffffffu, a1, off);
        a2 += __shfl_xor_sync(0xffffffffu, a2, off);
        a3 += __shfl_xor_sync(0xffffffffu, a3, off);
    }
    if (lane == 0) {
        float bs = __ldg(bias + n);
        out[(b0 + 0) * CDIM + n] = a0 + bs;
        out[(b0 + 1) * CDIM + n] = a1 + bs;
        out[(b0 + 2) * CDIM + n] = a2 + bs;
        out[(b0 + 3) * CDIM + n] = a3 + bs;
    }
}

// ---------------------------------------------------------------------------
// Entire GEMM chain, one launch. grid = GBLK x 256.
//   tmp0 = cond @ Wc^T + bc   (K=1024)
//   tmp1 = tmp0 @ Wv^T + bv   (K=768)
//   tmp0 = tmp1 @ Wa^T + ba   (K=768)
//   tmp1 = tmp0 @ Wo^T + bo   (K=768)  = proj
// ---------------------------------------------------------------------------
__global__ void __launch_bounds__(256, 4) gemm_chain(
    const float* __restrict__ conditioning,
    const float* __restrict__ w_cond,  const float* __restrict__ b_cond,
    const float* __restrict__ wv,      const float* __restrict__ bv,
    const float* __restrict__ attn_w,  const float* __restrict__ attn_b,
    const float* __restrict__ w_out,   const float* __restrict__ b_out)
{
    gemm_phase<KCOND / 4, false>(conditioning, w_cond, b_cond, g_tmp0);
    grid_sync(GBLK);
    gemm_phase<CDIM / 4, true >(g_tmp0, wv,     bv,     g_tmp1);
    grid_sync(2 * GBLK);
    gemm_phase<CDIM / 4, true >(g_tmp1, attn_w, attn_b, g_tmp0);
    grid_sync(3 * GBLK);
    gemm_phase<CDIM / 4, true >(g_tmp0, w_out,  b_out,  g_tmp1);
}

// ---------------------------------------------------------------------------
// Fused broadcast-add + LayerNorm(C). Hybrid tile: 12 c-rows per thread in
// registers + 12 c-rows in SMEM (48 KB) -> 3 blocks/SM. (Round-6 winner.)
// Thread map: p4 = tid&7 (float4 slot of 32-pixel row), c0 = tid>>3 (0..31).
// Spatial read exactly once from DRAM.
// ---------------------------------------------------------------------------
__global__ void __launch_bounds__(THREADS, 3) fused_add_ln(
    const float* __restrict__ spatial,
    const float* __restrict__ proj,
    const float* __restrict__ gamma,
    const float* __restrict__ beta,
    float* __restrict__ out)
{
    extern __shared__ float smem[];
    float* tile   = smem;                              // (24-REG_IT)*32*PIX
    float* psum   = tile + (24 - REG_IT) * 32 * PIX;   // 8*PIX
    float* psq    = psum + 8 * PIX;                    // 8*PIX
    float* mean_s = psq  + 8 * PIX;                    // PIX
    float* rstd_s = mean_s + PIX;                      // PIX

    const int tid = threadIdx.x;
    const int b   = blockIdx.x >> 7;          // SDIM/PIX = 128 blocks/batch
    const int s0  = (blockIdx.x & 127) * PIX;

    const int p4   = tid & 7;                 // float4 slot within 32-pixel row
    const int c0   = tid >> 3;                // 0..31
    const int warp = tid >> 5;
    const int lane = tid & 31;

    const size_t gbase = (size_t)b * CDIM * SDIM + s0 + p4 * 4;
    const float* projb = proj + b * CDIM;

    float4 v[REG_IT];
    float acc[4] = {0.f, 0.f, 0.f, 0.f};
    float asq[4] = {0.f, 0.f, 0.f, 0.f};

    // ---- load + broadcast add + register stats (one DRAM read) ----
#pragma unroll
    for (int it = 0; it < 24; it++) {
        const int c = c0 + it * 32;
        float4 x = *(const float4*)(spatial + gbase + (size_t)c * SDIM);
        float pj = __ldg(projb + c);
        x.x += pj; x.y += pj; x.z += pj; x.w += pj;
        acc[0] += x.x; asq[0] += x.x * x.x;
        acc[1] += x.y; asq[1] += x.y * x.y;
        acc[2] += x.z; asq[2] += x.z * x.z;
        acc[3] += x.w; asq[3] += x.w * x.w;
        if (it < REG_IT) {
            v[it] = x;
        } else {
            *(float4*)(tile + ((it - REG_IT) * 32 + c0) * PIX + p4 * 4) = x;
        }
    }

    // ---- combine the 4 same-p4 lanes of this warp (lane bits 3,4) ----
#pragma unroll
    for (int q = 0; q < 4; q++) {
        acc[q] += __shfl_xor_sync(0xffffffffu, acc[q], 8);
        acc[q] += __shfl_xor_sync(0xffffffffu, acc[q], 16);
        asq[q] += __shfl_xor_sync(0xffffffffu, asq[q], 8);
        asq[q] += __shfl_xor_sync(0xffffffffu, asq[q], 16);
    }
    if (lane == p4) {                         // lanes 0..7
#pragma unroll
        for (int q = 0; q < 4; q++) {
            psum[warp * PIX + p4 * 4 + q] = acc[q];
            psq [warp * PIX + p4 * 4 + q] = asq[q];
        }
    }
    __syncthreads();

    // ---- final per-pixel stats ----
    if (tid < PIX) {
        float s = 0.f, sq = 0.f;
#pragma unroll
        for (int w = 0; w < 8; w++) { s += psum[w * PIX + tid]; sq += psq[w * PIX + tid]; }
        const float inv = 1.0f / CDIM;
        float mu  = s * inv;
        float var = sq * inv - mu * mu;
        mean_s[tid] = mu;
        rstd_s[tid] = rsqrtf(var + 1e-5f);
    }
    __syncthreads();

    // ---- normalize + store (register rows first, then smem rows) ----
    const float4 mu4 = *(const float4*)(mean_s + p4 * 4);
    const float4 rs4 = *(const float4*)(rstd_s + p4 * 4);
#pragma unroll
    for (int it = 0; it < REG_IT; it++) {
        const int c = c0 + it * 32;
        float g  = __ldg(gamma + c);
        float bt = __ldg(beta + c);
        float4 x = v[it];
        x.x = (x.x - mu4.x) * rs4.x * g + bt;
        x.y = (x.y - mu4.y) * rs4.y * g + bt;
        x.z = (x.z - mu4.z) * rs4.z * g + bt;
        x.w = (x.w - mu4.w) * rs4.w * g + bt;
        *(float4*)(out + gbase + (size_t)c * SDIM) = x;
    }
#pragma unroll
    for (int it = REG_IT; it < 24; it++) {
        const int c = c0 + it * 32;
        float g  = __ldg(gamma + c);
        float bt = __ldg(beta + c);
        float4 x = *(const float4*)(tile + ((it - REG_IT) * 32 + c0) * PIX + p4 * 4);
        x.x = (x.x - mu4.x) * rs4.x * g + bt;
        x.y = (x.y - mu4.y) * rs4.y * g + bt;
        x.z = (x.z - mu4.z) * rs4.z * g + bt;
        x.w = (x.w - mu4.w) * rs4.w * g + bt;
        *(float4*)(out + gbase + (size_t)c * SDIM) = x;
    }
}

// ---------------------------------------------------------------------------
// Launcher
// ---------------------------------------------------------------------------
extern "C" void kernel_launch(void* const* d_in, const int* in_sizes, int n_in,
                              void* d_out, int out_size)
{
    const float* spatial     = (const float*)d_in[0];
    const float* conditioning= (const float*)d_in[1];
    const float* w_cond      = (const float*)d_in[2];
    const float* b_cond      = (const float*)d_in[3];
    const float* in_proj_w   = (const float*)d_in[4];
    const float* in_proj_b   = (const float*)d_in[5];
    const float* attn_out_w  = (const float*)d_in[6];
    const float* attn_out_b  = (const float*)d_in[7];
    const float* w_out       = (const float*)d_in[8];
    const float* b_out       = (const float*)d_in[9];
    const float* ln_gamma    = (const float*)d_in[10];
    const float* ln_beta     = (const float*)d_in[11];
    float* out = (float*)d_out;

    float* tmp1;
    cudaGetSymbolAddress((void**)&tmp1, g_tmp1);
    unsigned* bar;
    cudaGetSymbolAddress((void**)&bar, g_barrier);

    const int smem_bytes =
        ((24 - REG_IT) * 32 * PIX + 16 * PIX + 2 * PIX) * sizeof(float);
    cudaFuncSetAttribute(fused_add_ln, cudaFuncAttributeMaxDynamicSharedMemorySize,
                         smem_bytes);

    // reset grid barrier (graph-capturable memset node)
    cudaMemsetAsync(bar, 0, sizeof(unsigned), 0);

    // entire GEMM chain in one launch
    gemm_chain<<<GBLK, 256>>>(conditioning,
                              w_cond, b_cond,
                              in_proj_w + 2 * CDIM * CDIM, in_proj_b + 2 * CDIM,
                              attn_out_w, attn_out_b,
                              w_out, b_out);

    // fused add + layernorm (proj lives in g_tmp1)
    fused_add_ln<<<BATCH * (SDIM / PIX), THREADS, smem_bytes>>>(
        spatial, tmp1, ln_gamma, ln_beta, out);
}

// round 16
// speedup vs baseline: 1.0966x; 1.0678x over previous
#include <cuda_runtime.h>
#include <cstdint>

// ---------------------------------------------------------------------------
// Problem constants
// ---------------------------------------------------------------------------
#define BATCH 16
#define CDIM  768
#define SDIM  4096          // H*W = 64*64
#define KCOND 1024

#define PIX     32          // pixels per LN block
#define THREADS 256

#define GBLK    384         // chain grid: 384 blocks x 8 warps = 3072 warps

// ---------------------------------------------------------------------------
// Scratch (no allocations allowed -> device globals)
// ---------------------------------------------------------------------------
__device__ __align__(16) float g_tmp0[BATCH * CDIM];
__device__ __align__(16) float g_tmp1[BATCH * CDIM];
__device__ unsigned g_barrier;

// ---------------------------------------------------------------------------
// Grid-wide software barrier. ALL GBLK blocks co-resident:
// __launch_bounds__(256,3) -> 3 blocks/SM x 148 = 444 >= 384.
// Counter reset to 0 by a memset node before each launch.
// ---------------------------------------------------------------------------
__device__ __forceinline__ void grid_sync(unsigned target) {
    __syncthreads();
    if (threadIdx.x == 0) {
        __threadfence();                       // release our writes
        atomicAdd(&g_barrier, 1u);
        volatile unsigned* p = &g_barrier;
        while (*p < target) __nanosleep(32);
        __threadfence();                       // acquire others' writes
    }
    __syncthreads();
}

// ---------------------------------------------------------------------------
// One GEMM phase: out[b,n] = bias[n] + sum_k X[b,k] * W[n,k], B=16, N=768.
// 3072 warps: warp -> (column n, batch quad). Fully-unrolled K loop:
// 5 float4 LDGs per iter, 30-40 outstanding loads per warp.
// XCG: X written by a previous phase -> bypass (possibly stale) L1.
// ---------------------------------------------------------------------------
template<int K4, bool XCG>
__device__ __forceinline__ void gemm_phase(
    const float* __restrict__ X, const float* __restrict__ W,
    const float* __restrict__ bias, float* __restrict__ out)
{
    const int gw   = blockIdx.x * 8 + (threadIdx.x >> 5);  // 0..3071
    const int lane = threadIdx.x & 31;
    const int n    = gw >> 2;                 // 0..767
    const int b0   = (gw & 3) * 4;            // batch quad

    const float4* W4 = (const float4*)W + (size_t)n * K4;
    const float4* X4 = (const float4*)X + (size_t)b0 * K4;

    float a0 = 0.f, a1 = 0.f, a2 = 0.f, a3 = 0.f;
#pragma unroll
    for (int i = 0; i < K4 / 32; i++) {
        const int k4 = lane + i * 32;
        float4 w  = __ldg(W4 + k4);
        float4 x0 = XCG ? __ldcg(X4 + k4)          : __ldg(X4 + k4);
        float4 x1 = XCG ? __ldcg(X4 + K4 + k4)     : __ldg(X4 + K4 + k4);
        float4 x2 = XCG ? __ldcg(X4 + 2 * K4 + k4) : __ldg(X4 + 2 * K4 + k4);
        float4 x3 = XCG ? __ldcg(X4 + 3 * K4 + k4) : __ldg(X4 + 3 * K4 + k4);
        a0 += w.x*x0.x + w.y*x0.y + w.z*x0.z + w.w*x0.w;
        a1 += w.x*x1.x + w.y*x1.y + w.z*x1.z + w.w*x1.w;
        a2 += w.x*x2.x + w.y*x2.y + w.z*x2.z + w.w*x2.w;
        a3 += w.x*x3.x + w.y*x3.y + w.z*x3.z + w.w*x3.w;
    }
#pragma unroll
    for (int off = 16; off; off >>= 1) {
        a0 += __shfl_xor_sync(0xffffffffu, a0, off);
        a1 += __shfl_xor_sync(0xffffffffu, a1, off);
        a2 += __shfl_xor_sync(0xffffffffu, a2, off);
        a3 += __shfl_xor_sync(0xffffffffu, a3, off);
    }
    if (lane == 0) {
        float bs = __ldg(bias + n);
        out[(b0 + 0) * CDIM + n] = a0 + bs;
        out[(b0 + 1) * CDIM + n] = a1 + bs;
        out[(b0 + 2) * CDIM + n] = a2 + bs;
        out[(b0 + 3) * CDIM + n] = a3 + bs;
    }
}

// ---------------------------------------------------------------------------
// Entire GEMM chain, one launch. grid = GBLK x 256, 3 blocks/SM (no spills).
// ---------------------------------------------------------------------------
__global__ void __launch_bounds__(256, 3) gemm_chain(
    const float* __restrict__ conditioning,
    const float* __restrict__ w_cond,  const float* __restrict__ b_cond,
    const float* __restrict__ wv,      const float* __restrict__ bv,
    const float* __restrict__ attn_w,  const float* __restrict__ attn_b,
    const float* __restrict__ w_out,   const float* __restrict__ b_out)
{
    gemm_phase<KCOND / 4, false>(conditioning, w_cond, b_cond, g_tmp0);
    grid_sync(GBLK);
    gemm_phase<CDIM / 4, true >(g_tmp0, wv,     bv,     g_tmp1);
    grid_sync(2 * GBLK);
    gemm_phase<CDIM / 4, true >(g_tmp1, attn_w, attn_b, g_tmp0);
    grid_sync(3 * GBLK);
    gemm_phase<CDIM / 4, true >(g_tmp0, w_out,  b_out,  g_tmp1);
}

// ---------------------------------------------------------------------------
// Fused broadcast-add + LayerNorm(C), register-resident tile (round-4 winner,
// measured 66.0 us / 66.8% DRAM). PIX=32 pixels/block; thread holds 24 float4
// in registers. Stats via shfl + tiny smem cross-warp reduce.
// Thread map: p4 = tid&7 (float4 slot of 32-pixel row), c0 = tid>>3 (0..31).
// Spatial read exactly once from DRAM.
// ---------------------------------------------------------------------------
__global__ void __launch_bounds__(THREADS, 2) fused_add_ln(
    const float* __restrict__ spatial,
    const float* __restrict__ proj,
    const float* __restrict__ gamma,
    const float* __restrict__ beta,
    float* __restrict__ out)
{
    __shared__ float psum[8 * PIX];
    __shared__ float psq [8 * PIX];
    __shared__ float mean_s[PIX];
    __shared__ float rstd_s[PIX];

    const int tid = threadIdx.x;
    const int b   = blockIdx.x >> 7;          // SDIM/PIX = 128 blocks/batch
    const int s0  = (blockIdx.x & 127) * PIX;

    const int p4   = tid & 7;                 // float4 slot within 32-pixel row
    const int c0   = tid >> 3;                // 0..31
    const int warp = tid >> 5;
    const int lane = tid & 31;

    const size_t gbase = (size_t)b * CDIM * SDIM + s0 + p4 * 4;
    const float* projb = proj + b * CDIM;

    float4 v[24];                             // CDIM/32 = 24 rows per thread
    float acc[4] = {0.f, 0.f, 0.f, 0.f};
    float asq[4] = {0.f, 0.f, 0.f, 0.f};

    // ---- load + broadcast add + register stats (one DRAM read) ----
#pragma unroll
    for (int it = 0; it < 24; it++) {
        const int c = c0 + it * 32;
        float4 x = *(const float4*)(spatial + gbase + (size_t)c * SDIM);
        float pj = __ldg(projb + c);
        x.x += pj; x.y += pj; x.z += pj; x.w += pj;
        acc[0] += x.x; asq[0] += x.x * x.x;
        acc[1] += x.y; asq[1] += x.y * x.y;
        acc[2] += x.z; asq[2] += x.z * x.z;
        acc[3] += x.w; asq[3] += x.w * x.w;
        v[it] = x;
    }

    // ---- combine the 4 same-p4 lanes of this warp (lane bits 3,4) ----
#pragma unroll
    for (int q = 0; q < 4; q++) {
        acc[q] += __shfl_xor_sync(0xffffffffu, acc[q], 8);
        acc[q] += __shfl_xor_sync(0xffffffffu, acc[q], 16);
        asq[q] += __shfl_xor_sync(0xffffffffu, asq[q], 8);
        asq[q] += __shfl_xor_sync(0xffffffffu, asq[q], 16);
    }
    if (lane == p4) {                         // lanes 0..7
#pragma unroll
        for (int q = 0; q < 4; q++) {
            psum[warp * PIX + p4 * 4 + q] = acc[q];
            psq [warp * PIX + p4 * 4 + q] = asq[q];
        }
    }
    __syncthreads();

    // ---- final per-pixel stats ----
    if (tid < PIX) {
        float s = 0.f, sq = 0.f;
#pragma unroll
        for (int w = 0; w < 8; w++) { s += psum[w * PIX + tid]; sq += psq[w * PIX + tid]; }
        const float inv = 1.0f / CDIM;
        float mu  = s * inv;
        float var = sq * inv - mu * mu;
        mean_s[tid] = mu;
        rstd_s[tid] = rsqrtf(var + 1e-5f);
    }
    __syncthreads();

    // ---- normalize registers + store ----
    const float4 mu4 = *(const float4*)(mean_s + p4 * 4);
    const float4 rs4 = *(const float4*)(rstd_s + p4 * 4);
#pragma unroll
    for (int it = 0; it < 24; it++) {
        const int c = c0 + it * 32;
        float g  = __ldg(gamma + c);
        float bt = __ldg(beta + c);
        float4 x = v[it];
        x.x = (x.x - mu4.x) * rs4.x * g + bt;
        x.y = (x.y - mu4.y) * rs4.y * g + bt;
        x.z = (x.z - mu4.z) * rs4.z * g + bt;
        x.w = (x.w - mu4.w) * rs4.w * g + bt;
        *(float4*)(out + gbase + (size_t)c * SDIM) = x;
    }
}

// ---------------------------------------------------------------------------
// Launcher
// ---------------------------------------------------------------------------
extern "C" void kernel_launch(void* const* d_in, const int* in_sizes, int n_in,
                              void* d_out, int out_size)
{
    const float* spatial     = (const float*)d_in[0];
    const float* conditioning= (const float*)d_in[1];
    const float* w_cond      = (const float*)d_in[2];
    const float* b_cond      = (const float*)d_in[3];
    const float* in_proj_w   = (const float*)d_in[4];
    const float* in_proj_b   = (const float*)d_in[5];
    const float* attn_out_w  = (const float*)d_in[6];
    const float* attn_out_b  = (const float*)d_in[7];
    const float* w_out       = (const float*)d_in[8];
    const float* b_out       = (const float*)d_in[9];
    const float* ln_gamma    = (const float*)d_in[10];
    const float* ln_beta     = (const float*)d_in[11];
    float* out = (float*)d_out;

    float* tmp1;
    cudaGetSymbolAddress((void**)&tmp1, g_tmp1);
    unsigned* bar;
    cudaGetSymbolAddress((void**)&bar, g_barrier);

    // reset grid barrier (graph-capturable memset node)
    cudaMemsetAsync(bar, 0, sizeof(unsigned), 0);

    // entire GEMM chain in one launch
    gemm_chain<<<GBLK, 256>>>(conditioning,
                              w_cond, b_cond,
                              in_proj_w + 2 * CDIM * CDIM, in_proj_b + 2 * CDIM,
                              attn_out_w, attn_out_b,
                              w_out, b_out);

    // fused add + layernorm (proj lives in g_tmp1)
    fused_add_ln<<<BATCH * (SDIM / PIX), THREADS>>>(
        spatial, tmp1, ln_gamma, ln_beta, out);
}

// round 17
// speedup vs baseline: 1.1164x; 1.0181x over previous
#include <cuda_runtime.h>
#include <cstdint>

// ---------------------------------------------------------------------------
// Problem constants
// ---------------------------------------------------------------------------
#define BATCH 16
#define CDIM  768
#define SDIM  4096          // H*W = 64*64
#define KCOND 1024

#define PIX      32         // pixels per LN block
#define LNTHR    384        // LN threads: 48 c-rows per iteration, 16 iters
#define LNIT     16         // CDIM / 48
#define GBLK     384        // chain grid: 384 blocks x 8 warps = 3072 warps

// ---------------------------------------------------------------------------
// Scratch (no allocations allowed -> device globals)
// ---------------------------------------------------------------------------
__device__ __align__(16) float g_tmp0[BATCH * CDIM];
__device__ __align__(16) float g_tmp1[BATCH * CDIM];
__device__ unsigned g_barrier;     // zero-init at load; kernel restores 0 on exit

// ---------------------------------------------------------------------------
// Grid-wide software barrier. ALL GBLK blocks co-resident:
// __launch_bounds__(256,3) -> 3 blocks/SM x 148 = 444 >= 384.
// ---------------------------------------------------------------------------
__device__ __forceinline__ void grid_sync(unsigned target) {
    __syncthreads();
    if (threadIdx.x == 0) {
        __threadfence();                       // release our writes
        atomicAdd(&g_barrier, 1u);
        volatile unsigned* p = &g_barrier;
        while (*p < target) __nanosleep(32);
        __threadfence();                       // acquire others' writes
    }
    __syncthreads();
}

// ---------------------------------------------------------------------------
// One GEMM phase: out[b,n] = bias[n] + sum_k X[b,k] * W[n,k], B=16, N=768.
// 3072 warps: warp -> (column n, batch quad). Fully-unrolled K loop.
// XCG: X written by a previous phase -> bypass (possibly stale) L1.
// ---------------------------------------------------------------------------
template<int K4, bool XCG>
__device__ __forceinline__ void gemm_phase(
    const float* __restrict__ X, const float* __restrict__ W,
    const float* __restrict__ bias, float* __restrict__ out)
{
    const int gw   = blockIdx.x * 8 + (threadIdx.x >> 5);  // 0..3071
    const int lane = threadIdx.x & 31;
    const int n    = gw >> 2;                 // 0..767
    const int b0   = (gw & 3) * 4;            // batch quad

    const float4* W4 = (const float4*)W + (size_t)n * K4;
    const float4* X4 = (const float4*)X + (size_t)b0 * K4;

    float a0 = 0.f, a1 = 0.f, a2 = 0.f, a3 = 0.f;
#pragma unroll
    for (int i = 0; i < K4 / 32; i++) {
        const int k4 = lane + i * 32;
        float4 w  = __ldg(W4 + k4);
        float4 x0 = XCG ? __ldcg(X4 + k4)          : __ldg(X4 + k4);
        float4 x1 = XCG ? __ldcg(X4 + K4 + k4)     : __ldg(X4 + K4 + k4);
        float4 x2 = XCG ? __ldcg(X4 + 2 * K4 + k4) : __ldg(X4 + 2 * K4 + k4);
        float4 x3 = XCG ? __ldcg(X4 + 3 * K4 + k4) : __ldg(X4 + 3 * K4 + k4);
        a0 += w.x*x0.x + w.y*x0.y + w.z*x0.z + w.w*x0.w;
        a1 += w.x*x1.x + w.y*x1.y + w.z*x1.z + w.w*x1.w;
        a2 += w.x*x2.x + w.y*x2.y + w.z*x2.z + w.w*x2.w;
        a3 += w.x*x3.x + w.y*x3.y + w.z*x3.z + w.w*x3.w;
    }
#pragma unroll
    for (int off = 16; off; off >>= 1) {
        a0 += __shfl_xor_sync(0xffffffffu, a0, off);
        a1 += __shfl_xor_sync(0xffffffffu, a1, off);
        a2 += __shfl_xor_sync(0xffffffffu, a2, off);
        a3 += __shfl_xor_sync(0xffffffffu, a3, off);
    }
    if (lane == 0) {
        float bs = __ldg(bias + n);
        out[(b0 + 0) * CDIM + n] = a0 + bs;
        out[(b0 + 1) * CDIM + n] = a1 + bs;
        out[(b0 + 2) * CDIM + n] = a2 + bs;
        out[(b0 + 3) * CDIM + n] = a3 + bs;
    }
}

// ---------------------------------------------------------------------------
// Entire GEMM chain, one launch. grid = GBLK x 256, 3 blocks/SM.
// Barrier counter self-resets (no memset node needed).
// ---------------------------------------------------------------------------
__global__ void __launch_bounds__(256, 3) gemm_chain(
    const float* __restrict__ conditioning,
    const float* __restrict__ w_cond,  const float* __restrict__ b_cond,
    const float* __restrict__ wv,      const float* __restrict__ bv,
    const float* __restrict__ attn_w,  const float* __restrict__ attn_b,
    const float* __restrict__ w_out,   const float* __restrict__ b_out)
{
    gemm_phase<KCOND / 4, false>(conditioning, w_cond, b_cond, g_tmp0);
    grid_sync(GBLK);
    gemm_phase<CDIM / 4, true >(g_tmp0, wv,     bv,     g_tmp1);
    grid_sync(2 * GBLK);
    gemm_phase<CDIM / 4, true >(g_tmp1, attn_w, attn_b, g_tmp0);
    grid_sync(3 * GBLK);
    gemm_phase<CDIM / 4, true >(g_tmp0, w_out,  b_out,  g_tmp1);

    // final arrive; block 0 waits for everyone then restores the counter to 0
    __syncthreads();
    if (threadIdx.x == 0) {
        __threadfence();
        atomicAdd(&g_barrier, 1u);
        if (blockIdx.x == 0) {
            volatile unsigned* p = &g_barrier;
            while (*p < 4u * GBLK) __nanosleep(32);
            *p = 0u;                      // restore for the next replay
            __threadfence();
        }
    }
}

// ---------------------------------------------------------------------------
// Fused broadcast-add + LayerNorm(C), register-resident tile.
// 384 threads/block, 16 c-rows per thread (v[16], ~84 regs) -> 2 blocks/SM
// = 24 warps (occ 50%, up from 16 warps at 256thr/128regs).
// Thread map: p4 = tid&7 (float4 slot of 32-pixel row), c0 = tid>>3 (0..47).
// Spatial read exactly once from DRAM.
// ---------------------------------------------------------------------------
__global__ void __launch_bounds__(LNTHR, 2) fused_add_ln(
    const float* __restrict__ spatial,
    const float* __restrict__ proj,
    const float* __restrict__ gamma,
    const float* __restrict__ beta,
    float* __restrict__ out)
{
    __shared__ float psum[12 * PIX];
    __shared__ float psq [12 * PIX];
    __shared__ float mean_s[PIX];
    __shared__ float rstd_s[PIX];

    const int tid = threadIdx.x;
    const int b   = blockIdx.x >> 7;          // SDIM/PIX = 128 blocks/batch
    const int s0  = (blockIdx.x & 127) * PIX;

    const int p4   = tid & 7;                 // float4 slot within 32-pixel row
    const int c0   = tid >> 3;                // 0..47
    const int warp = tid >> 5;                // 0..11
    const int lane = tid & 31;

    const size_t gbase = (size_t)b * CDIM * SDIM + s0 + p4 * 4;
    const float* projb = proj + b * CDIM;

    float4 v[LNIT];                           // 16 rows per thread
    float acc[4] = {0.f, 0.f, 0.f, 0.f};
    float asq[4] = {0.f, 0.f, 0.f, 0.f};

    // ---- load + broadcast add + register stats (one DRAM read) ----
#pragma unroll
    for (int it = 0; it < LNIT; it++) {
        const int c = c0 + it * 48;
        float4 x = *(const float4*)(spatial + gbase + (size_t)c * SDIM);
        float pj = __ldg(projb + c);
        x.x += pj; x.y += pj; x.z += pj; x.w += pj;
        acc[0] += x.x; asq[0] += x.x * x.x;
        acc[1] += x.y; asq[1] += x.y * x.y;
        acc[2] += x.z; asq[2] += x.z * x.z;
        acc[3] += x.w; asq[3] += x.w * x.w;
        v[it] = x;
    }

    // ---- combine the 4 same-p4 lanes of this warp (lane bits 3,4) ----
#pragma unroll
    for (int q = 0; q < 4; q++) {
        acc[q] += __shfl_xor_sync(0xffffffffu, acc[q], 8);
        acc[q] += __shfl_xor_sync(0xffffffffu, acc[q], 16);
        asq[q] += __shfl_xor_sync(0xffffffffu, asq[q], 8);
        asq[q] += __shfl_xor_sync(0xffffffffu, asq[q], 16);
    }
    if (lane == p4) {                         // lanes 0..7
#pragma unroll
        for (int q = 0; q < 4; q++) {
            psum[warp * PIX + p4 * 4 + q] = acc[q];
            psq [warp * PIX + p4 * 4 + q] = asq[q];
        }
    }
    __syncthreads();

    // ---- final per-pixel stats ----
    if (tid < PIX) {
        float s = 0.f, sq = 0.f;
#pragma unroll
        for (int w = 0; w < 12; w++) { s += psum[w * PIX + tid]; sq += psq[w * PIX + tid]; }
        const float inv = 1.0f / CDIM;
        float mu  = s * inv;
        float var = sq * inv - mu * mu;
        mean_s[tid] = mu;
        rstd_s[tid] = rsqrtf(var + 1e-5f);
    }
    __syncthreads();

    // ---- normalize registers + store ----
    const float4 mu4 = *(const float4*)(mean_s + p4 * 4);
    const float4 rs4 = *(const float4*)(rstd_s + p4 * 4);
#pragma unroll
    for (int it = 0; it < LNIT; it++) {
        const int c = c0 + it * 48;
        float g  = __ldg(gamma + c);
        float bt = __ldg(beta + c);
        float4 x = v[it];
        x.x = (x.x - mu4.x) * rs4.x * g + bt;
        x.y = (x.y - mu4.y) * rs4.y * g + bt;
        x.z = (x.z - mu4.z) * rs4.z * g + bt;
        x.w = (x.w - mu4.w) * rs4.w * g + bt;
        *(float4*)(out + gbase + (size_t)c * SDIM) = x;
    }
}

// ---------------------------------------------------------------------------
// Launcher
// ---------------------------------------------------------------------------
extern "C" void kernel_launch(void* const* d_in, const int* in_sizes, int n_in,
                              void* d_out, int out_size)
{
    const float* spatial     = (const float*)d_in[0];
    const float* conditioning= (const float*)d_in[1];
    const float* w_cond      = (const float*)d_in[2];
    const float* b_cond      = (const float*)d_in[3];
    const float* in_proj_w   = (const float*)d_in[4];
    const float* in_proj_b   = (const float*)d_in[5];
    const float* attn_out_w  = (const float*)d_in[6];
    const float* attn_out_b  = (const float*)d_in[7];
    const float* w_out       = (const float*)d_in[8];
    const float* b_out       = (const float*)d_in[9];
    const float* ln_gamma    = (const float*)d_in[10];
    const float* ln_beta     = (const float*)d_in[11];
    float* out = (float*)d_out;

    float* tmp1;
    cudaGetSymbolAddress((void**)&tmp1, g_tmp1);

    // entire GEMM chain in one launch (barrier self-resets)
    gemm_chain<<<GBLK, 256>>>(conditioning,
                              w_cond, b_cond,
                              in_proj_w + 2 * CDIM * CDIM, in_proj_b + 2 * CDIM,
                              attn_out_w, attn_out_b,
                              w_out, b_out);

    // fused add + layernorm (proj lives in g_tmp1)
    fused_add_ln<<<BATCH * (SDIM / PIX), LNTHR>>>(
        spatial, tmp1, ln_gamma, ln_beta, out);
}